// round 15
// baseline (speedup 1.0000x reference)
#include <cuda_runtime.h>
#include <cuda_fp16.h>
#include <cstdint>

// Problem constants
#define B_     4096
#define D_INN  4096
#define D_PROJ 1024
#define N_CLS  32
#define NC0    32
#define NC1    64

// Output layout: (parent_logits, child0, child1, parent_proj, child_proj) flattened fp32
#define OFF_PLOG 0
#define OFF_C0   (B_ * N_CLS)                 // 131072
#define OFF_C1   (OFF_C0 + B_ * NC0)          // 262144
#define OFF_P    (OFF_C1 + B_ * NC1)          // 524288
#define OFF_S    (OFF_P + B_ * D_PROJ)        // 4718592

#define WSCALE 4096.0f
#define OSCALE (1.0f / 4096.0f)

// fp16 scratch + bucket/dependency state (static device globals)
__device__ __align__(16) __half g_xh[B_ * D_INN];            // 32 MB
__device__ __align__(16) __half g_wph[D_INN * D_PROJ];       // 8 MB (x WSCALE)
__device__ __align__(16) __half g_wsh[D_INN * D_PROJ];       // 8 MB (x WSCALE)
__device__ __align__(16) __half g_ph[B_ * D_PROJ];           // 8 MB, P fp16
__device__ __align__(16) __half g_sh[B_ * D_PROJ];           // 8 MB, S fp16
__device__ __align__(16) __half g_cwh[N_CLS * 96 * D_PROJ];  // 6 MB, merged cw (x WSCALE)
__device__ __align__(16) __half g_wch[D_PROJ * N_CLS];       // 64 KB, Wc (x WSCALE)
__device__ int g_cnt[N_CLS];
__device__ int g_idx[N_CLS][B_];
// dependency counters / flags (zeroed each call by zero_kernel)
__device__ int g_pdone[32];      // per m-row-block of P (target 8)
__device__ int g_sdone;          // S CTAs finished (target 256)
__device__ int g_bdone;          // bucket blocks finished (target 32)
__device__ int g_wcdone;         // Wc-convert blocks finished (target 32)
__device__ int g_cwdone[N_CLS];  // per-class cw-convert quarters (target 4)
__device__ int g_xf[32][8];      // x chunk ready (rows by*128, k bx*512)
__device__ int g_wsf[8][8];      // Ws chunk ready (slab bx, k c*512)
__device__ int g_wpf[8][8];      // Wp chunk ready

// ===========================================================================
// helpers
// ===========================================================================
__device__ __forceinline__ uint32_t smem_u32(const void* p) {
    uint32_t a;
    asm("{ .reg .u64 t; cvta.to.shared.u64 t, %1; cvt.u32.u64 %0, t; }" : "=r"(a) : "l"(p));
    return a;
}

__device__ __forceinline__ uint32_t f2h2(float hi, float lo) {
    uint32_t r;
    asm("cvt.rn.f16x2.f32 %0, %1, %2;" : "=r"(r) : "f"(hi), "f"(lo));
    return r;
}

__device__ __forceinline__ void ldsm_x4(uint32_t* r, uint32_t addr) {
    asm volatile("ldmatrix.sync.aligned.m8n8.x4.shared.b16 {%0,%1,%2,%3}, [%4];"
                 : "=r"(r[0]), "=r"(r[1]), "=r"(r[2]), "=r"(r[3]) : "r"(addr));
}
__device__ __forceinline__ void ldsm_x4_t(uint32_t* r, uint32_t addr) {
    asm volatile("ldmatrix.sync.aligned.m8n8.x4.trans.shared.b16 {%0,%1,%2,%3}, [%4];"
                 : "=r"(r[0]), "=r"(r[1]), "=r"(r[2]), "=r"(r[3]) : "r"(addr));
}

__device__ __forceinline__ void mma_f16(float* d, const uint32_t* a, const uint32_t* b) {
    asm volatile(
        "mma.sync.aligned.m16n8k16.row.col.f32.f16.f16.f32 "
        "{%0,%1,%2,%3}, {%4,%5,%6,%7}, {%8,%9}, {%0,%1,%2,%3};"
        : "+f"(d[0]), "+f"(d[1]), "+f"(d[2]), "+f"(d[3])
        : "r"(a[0]), "r"(a[1]), "r"(a[2]), "r"(a[3]), "r"(b[0]), "r"(b[1]));
}

#define CP_ASYNC16(saddr, gaddr) \
    asm volatile("cp.async.cg.shared.global [%0], [%1], 16;" :: "r"(saddr), "l"(gaddr))
#define CP_COMMIT() asm volatile("cp.async.commit_group;" ::: "memory")
#define CP_WAIT1()  asm volatile("cp.async.wait_group 1;"  ::: "memory")

// Completion signal: all threads' stores -> fence -> sync -> one atomic.
__device__ __forceinline__ void signal_done(int* ctr) {
    __threadfence();
    __syncthreads();
    if (threadIdx.x == 0) atomicAdd(ctr, 1);
}
// Spin until *ctr >= target (device-scope atomic read), then fence.
__device__ __forceinline__ void spin_until(int* ctr, int target) {
    if (threadIdx.x == 0)
        while (atomicAdd(ctr, 0) < target) __nanosleep(128);
    __syncthreads();
    __threadfence();
}
// Spin on a 0/1 flag (acquire).
__device__ __forceinline__ void spin_flag(int* f) {
    if (threadIdx.x == 0)
        while (atomicAdd(f, 0) == 0) __nanosleep(64);
    __syncthreads();
    __threadfence();
}

// ===========================================================================
// K0: zero all dependency counters / flags (tiny, 1 block x 256 threads)
// ===========================================================================
__global__ void zero_kernel() {
    const int t = threadIdx.x;
    (&g_xf[0][0])[t] = 0;                    // 256 flags
    if (t < 64) { (&g_wsf[0][0])[t] = 0; (&g_wpf[0][0])[t] = 0; }
    if (t < 32) { g_cnt[t] = 0; g_pdone[t] = 0; g_cwdone[t] = 0; }
    if (t == 65) g_sdone = 0;
    if (t == 66) g_bdone = 0;
    if (t == 67) g_wcdone = 0;
}

// ===========================================================================
// Mega kernel, grid (8, 32, 3), 128 threads:
// z=0: S = x@Ws GEMM; each S-CTA first converts its x chunk (rows by*128,
//      k bx*512 -- FULL 8192 f4-pairs) + a Ws/Wp chunk for by<16; sets flags.
//      GEMM polls chunk flags every 8th k-iter (hidden under CP_WAIT1).
// z=1: P = x@Wp GEMM; no convert duty; polls g_xf / g_wpf.
// z=2: flat<32 bucket; 32..63 plog (convert Wc, wait, TC plog);
//      64..191 child (convert cw quarter, wait, TC child); rest exit.
// ===========================================================================
#define STAGES 3
#define BKH    64
#define A_ST_BYTES (128 * 128)               // 16384
#define B_ST_BYTES (64 * 256)                // 16384
#define ST_BYTES   (A_ST_BYTES + B_ST_BYTES) // 32768
#define SMEM_MEGA  (STAGES * ST_BYTES)       // 98304

#define STP (16384 + 64 * 80)    // 21504  (plog stage)
#define STC (16384 + 96 * 128)   // 28672  (child stage)

__global__ __launch_bounds__(128, 2)
void mega_kernel(const float* __restrict__ x, const int* __restrict__ y,
                 const float* __restrict__ Wp, const float* __restrict__ bp,
                 const float* __restrict__ Ws, const float* __restrict__ bs,
                 const float* __restrict__ Wc, const float* __restrict__ bc,
                 const float* __restrict__ cw0, const float* __restrict__ cb0,
                 const float* __restrict__ cw1, const float* __restrict__ cb1,
                 float* __restrict__ out)
{
    extern __shared__ char sm[];
    const uint32_t sb = smem_u32(sm);

    const int tid  = threadIdx.x;
    const int warp = tid >> 5;
    const int lane = tid & 31;
    const int lm_row = (lane & 7) + ((lane >> 3) & 1) * 8;  // 0..15
    const int hi     = lane >> 4;                           // 0..1
    const int rm     = lm_row & 7;
    const int gid    = lane >> 2;
    const int tig    = lane & 3;

    const int z = blockIdx.z;

    if (z <= 1) {
        // =================== GEMM planes (R10/R12 core) ===================
        const int bx = blockIdx.x;
        const int by = blockIdx.y;
        const __half* __restrict__ Wh   = (z == 0) ? g_wsh : g_wph;
        const float*  __restrict__ bias = (z == 0) ? bs : bp;
        float* __restrict__ C  = out + ((z == 0) ? OFF_S : OFF_P);
        __half* __restrict__ Ch = (z == 0) ? g_sh : g_ph;

        const int wm   = warp >> 1;   // 0..1
        const int wn   = warp & 1;    // 0..1
        const int mblk = by * 128;
        const int nblk = bx * 128;

        // -------- convert duties (S-plane only), BEFORE any spin --------
        if (z == 0) {
            // x chunk: rows [by*128,+128), k [bx*512,+512) = 8192 f4-pairs
            {
                const size_t rowb = (size_t)by * 128;
                const size_t kb   = (size_t)bx * 512;
                #pragma unroll 4
                for (int j = 0; j < 64; j++) {
                    const int p = tid + j * 128;       // 0..8191
                    const int r = p >> 6, q = p & 63;  // 64 pairs per 512-float row
                    const size_t f = (rowb + r) * D_INN + kb + (size_t)q * 8;
                    float4 v0 = *reinterpret_cast<const float4*>(x + f);
                    float4 v1 = *reinterpret_cast<const float4*>(x + f + 4);
                    uint4 h = { f2h2(v0.y, v0.x), f2h2(v0.w, v0.z),
                                f2h2(v1.y, v1.x), f2h2(v1.w, v1.z) };
                    *reinterpret_cast<uint4*>(&g_xh[f]) = h;
                }
            }
            // W chunk: by<8 -> Ws (slab bx, k by*512); by in [8,16) -> Wp.
            // chunk = 512 k-rows x 128 n = 8192 f4-pairs
            if (by < 16) {
                const float* Wsrc = (by < 8) ? Ws : Wp;
                __half* Wdst = (by < 8) ? g_wsh : g_wph;
                const int c = by & 7;
                const size_t kb = (size_t)c * 512;
                const size_t nb = (size_t)bx * 128;
                #pragma unroll 4
                for (int j = 0; j < 64; j++) {
                    const int p = tid + j * 128;        // 0..8191
                    const int kr = p >> 4, q = p & 15;  // 16 pairs per 128-float row
                    const size_t f = (kb + kr) * D_PROJ + nb + (size_t)q * 8;
                    float4 v0 = *reinterpret_cast<const float4*>(Wsrc + f);
                    float4 v1 = *reinterpret_cast<const float4*>(Wsrc + f + 4);
                    uint4 h = { f2h2(v0.y * WSCALE, v0.x * WSCALE), f2h2(v0.w * WSCALE, v0.z * WSCALE),
                                f2h2(v1.y * WSCALE, v1.x * WSCALE), f2h2(v1.w * WSCALE, v1.z * WSCALE) };
                    *reinterpret_cast<uint4*>(&Wdst[f]) = h;
                }
            }
            __threadfence();
            __syncthreads();
            if (tid == 0) {
                atomicExch(&g_xf[by][bx], 1);
                if (by < 8)       atomicExch(&g_wsf[bx][by], 1);
                else if (by < 16) atomicExch(&g_wpf[bx][by - 8], 1);
            }
        }

        int* xfl = &g_xf[by][0];
        int* wfl = (z == 0) ? &g_wsf[bx][0] : &g_wpf[bx][0];

        // chunk 0 must be ready before the pipeline prologue
        spin_flag(&xfl[0]);
        spin_flag(&wfl[0]);

        float acc[4][8][4];
        #pragma unroll
        for (int mt = 0; mt < 4; mt++)
            #pragma unroll
            for (int nt = 0; nt < 8; nt++)
                #pragma unroll
                for (int i = 0; i < 4; i++) acc[mt][nt][i] = 0.f;

        auto issue = [&](uint32_t abase, int t) {
            const uint32_t bbase = abase + A_ST_BYTES;
            #pragma unroll
            for (int j = 0; j < 8; j++) {
                const int id  = tid + 128 * j;
                const int row = id >> 3, c = id & 7;
                const __half* g = g_xh + (size_t)(mblk + row) * D_INN + t * BKH + c * 8;
                CP_ASYNC16(abase + row * 128 + ((c ^ (row & 7)) << 4), g);
            }
            #pragma unroll
            for (int j = 0; j < 8; j++) {
                const int id = tid + 128 * j;
                const int k  = id >> 4, c = id & 15;
                const __half* g = Wh + (size_t)(t * BKH + k) * D_PROJ + nblk + c * 8;
                CP_ASYNC16(bbase + k * 256 + ((c ^ (k & 7)) << 4), g);
            }
        };

        auto load_frags = [&](uint32_t abase, int s, uint32_t (&af)[4][4], uint32_t (&bf)[8][2]) {
            const uint32_t bbase = abase + A_ST_BYTES;
            #pragma unroll
            for (int mt = 0; mt < 4; mt++) {
                const int row0 = wm * 64 + mt * 16 + lm_row;
                ldsm_x4(af[mt], abase + (uint32_t)(row0 * 128)
                                      + ((uint32_t)((2 * s + hi) ^ rm) << 4));
            }
            #pragma unroll
            for (int nb = 0; nb < 4; nb++) {
                uint32_t r[4];
                const int krow = 16 * s + lm_row;
                ldsm_x4_t(r, bbase + (uint32_t)(krow * 256)
                                   + ((uint32_t)((wn * 8 + nb * 2 + hi) ^ rm) << 4));
                bf[2 * nb][0] = r[0]; bf[2 * nb][1] = r[1];
                bf[2 * nb + 1][0] = r[2]; bf[2 * nb + 1][1] = r[3];
            }
        };

        uint32_t afr[2][4][4], bfr[2][8][2];

        auto body = [&](int t, uint32_t cbase, uint32_t pbase) {
            // poll next chunk's flags (hidden under the cp.async wait below)
            if (((t + 2) & 7) == 0 && (t + 2) < 64) {
                const int c = (t + 2) >> 3;
                spin_flag(&xfl[c]);
                spin_flag(&wfl[c]);
            }
            CP_WAIT1();
            __syncthreads();

            load_frags(cbase, 0, afr[0], bfr[0]);

            if (t + 2 < 64)
                issue(pbase, t + 2);
            CP_COMMIT();

            #pragma unroll
            for (int s = 0; s < 4; s++) {
                if (s < 3)
                    load_frags(cbase, s + 1, afr[(s + 1) & 1], bfr[(s + 1) & 1]);
                const int cur = s & 1;
                #pragma unroll
                for (int mt = 0; mt < 4; mt++)
                    #pragma unroll
                    for (int nt = 0; nt < 8; nt++)
                        mma_f16(acc[mt][nt], afr[cur][mt], bfr[cur][nt]);
            }
        };

        const uint32_t s0 = sb, s1 = sb + ST_BYTES, s2 = sb + 2 * ST_BYTES;

        issue(s0, 0); CP_COMMIT();
        issue(s1, 1); CP_COMMIT();

        for (int t = 0; t < 63; t += 3) {
            body(t,     s0, s2);
            body(t + 1, s1, s0);
            body(t + 2, s2, s1);
        }
        body(63, s0, s2);

        #pragma unroll
        for (int mt = 0; mt < 4; mt++) {
            const int row = mblk + wm * 64 + mt * 16 + gid;
            #pragma unroll
            for (int nt = 0; nt < 8; nt++) {
                const int col = nblk + wn * 64 + nt * 8 + 2 * tig;
                const float b0 = bias[col], b1 = bias[col + 1];
                float2 v0 = { acc[mt][nt][0] * OSCALE + b0, acc[mt][nt][1] * OSCALE + b1 };
                float2 v1 = { acc[mt][nt][2] * OSCALE + b0, acc[mt][nt][3] * OSCALE + b1 };
                *reinterpret_cast<float2*>(&C[(size_t)row * D_PROJ + col])       = v0;
                *reinterpret_cast<float2*>(&C[(size_t)(row + 8) * D_PROJ + col]) = v1;
                *reinterpret_cast<uint32_t*>(&Ch[(size_t)row * D_PROJ + col])       = f2h2(v0.y, v0.x);
                *reinterpret_cast<uint32_t*>(&Ch[(size_t)(row + 8) * D_PROJ + col]) = f2h2(v1.y, v1.x);
            }
        }

        signal_done((z == 0) ? &g_sdone : &g_pdone[blockIdx.y]);
        return;
    }

    // ======================= z == 2 : tail plane =======================
    const int flat = blockIdx.x + 8 * blockIdx.y;   // 0..255

    if (flat < 32) {
        // ---- bucket: 32 blocks x 128 threads = 4096 samples ----
        const int b = flat * 128 + tid;
        const int c = y[b];
        const int p = atomicAdd(&g_cnt[c], 1);
        g_idx[c][p] = b;
        signal_done(&g_bdone);
        return;
    }

    if (flat < 64) {
        // ---- parent logits block ----
        const int by   = flat - 32;
        const int mblk = by * 128;

        // convert this block's Wc slice (128 pairs of float4)
        {
            const int q = by * 128 + tid;          // 0..4095
            const size_t f4 = (size_t)q * 2;
            float4 v0 = *reinterpret_cast<const float4*>(Wc + f4 * 4);
            float4 v1 = *reinterpret_cast<const float4*>(Wc + f4 * 4 + 4);
            uint4 h = { f2h2(v0.y * WSCALE, v0.x * WSCALE), f2h2(v0.w * WSCALE, v0.z * WSCALE),
                        f2h2(v1.y * WSCALE, v1.x * WSCALE), f2h2(v1.w * WSCALE, v1.z * WSCALE) };
            *reinterpret_cast<uint4*>(&g_wch[f4 * 4]) = h;
        }
        signal_done(&g_wcdone);
        spin_until(&g_wcdone, 32);
        spin_until(&g_pdone[by], 8);

        float acc[2][4][4];
        #pragma unroll
        for (int mt = 0; mt < 2; mt++)
            #pragma unroll
            for (int nt = 0; nt < 4; nt++)
                #pragma unroll
                for (int i = 0; i < 4; i++) acc[mt][nt][i] = 0.f;

        auto issue = [&](int slot, int t) {
            const uint32_t abase = sb + slot * STP;
            const uint32_t bbase = abase + 16384;
            #pragma unroll
            for (int j = 0; j < 8; j++) {
                const int id = tid + 128 * j;
                const int row = id >> 3, c = id & 7;
                const __half* g = g_ph + (size_t)(mblk + row) * D_PROJ + t * 64 + c * 8;
                CP_ASYNC16(abase + row * 128 + ((c ^ (row & 7)) << 4), g);
            }
            #pragma unroll
            for (int j = 0; j < 2; j++) {
                const int id = tid + 128 * j;
                const int row = id >> 2, c = id & 3;
                const __half* g = g_wch + (size_t)(t * 64 + row) * N_CLS + c * 8;
                CP_ASYNC16(bbase + row * 80 + c * 16, g);
            }
        };

        issue(0, 0); CP_COMMIT();
        issue(1, 1); CP_COMMIT();
        int cs = 0, ns_slot = 2;

        for (int t = 0; t < 16; t++) {
            CP_WAIT1();
            __syncthreads();
            const uint32_t abase = sb + cs * STP;
            const uint32_t bbase = abase + 16384;
            if (t + 2 < 16) issue(ns_slot, t + 2);
            CP_COMMIT();

            #pragma unroll
            for (int s = 0; s < 4; s++) {
                uint32_t afr[2][4], bfr[4][2];
                #pragma unroll
                for (int mt = 0; mt < 2; mt++) {
                    const int row0 = warp * 32 + mt * 16 + lm_row;
                    ldsm_x4(afr[mt], abase + (uint32_t)(row0 * 128)
                                           + ((uint32_t)((2 * s + hi) ^ rm) << 4));
                }
                #pragma unroll
                for (int nb = 0; nb < 2; nb++) {
                    uint32_t r[4];
                    const int krow = 16 * s + lm_row;
                    ldsm_x4_t(r, bbase + (uint32_t)(krow * 80)
                                       + (uint32_t)((nb * 2 + hi) * 16));
                    bfr[2 * nb][0] = r[0]; bfr[2 * nb][1] = r[1];
                    bfr[2 * nb + 1][0] = r[2]; bfr[2 * nb + 1][1] = r[3];
                }
                #pragma unroll
                for (int mt = 0; mt < 2; mt++)
                    #pragma unroll
                    for (int nt = 0; nt < 4; nt++)
                        mma_f16(acc[mt][nt], afr[mt], bfr[nt]);
            }
            cs      = (cs == 2) ? 0 : cs + 1;
            ns_slot = (ns_slot == 2) ? 0 : ns_slot + 1;
        }

        #pragma unroll
        for (int mt = 0; mt < 2; mt++) {
            const int row = mblk + warp * 32 + mt * 16 + gid;
            #pragma unroll
            for (int nt = 0; nt < 4; nt++) {
                const int col = nt * 8 + 2 * tig;
                const float b0 = bc[col], b1 = bc[col + 1];
                float2 v0 = { acc[mt][nt][0] * OSCALE + b0, acc[mt][nt][1] * OSCALE + b1 };
                float2 v1 = { acc[mt][nt][2] * OSCALE + b0, acc[mt][nt][3] * OSCALE + b1 };
                *reinterpret_cast<float2*>(&out[OFF_PLOG + row * N_CLS + col])       = v0;
                *reinterpret_cast<float2*>(&out[OFF_PLOG + (row + 8) * N_CLS + col]) = v1;
            }
        }
        return;
    }

    if (flat >= 192) return;

    // ---- child expert block ----
    const int cbk   = flat - 64;
    const int cls   = cbk >> 2;
    const int chunk = cbk & 3;

    // convert this block's quarter of the class cw slab
    {
        const float* w0 = cw0 + (size_t)cls * NC0 * D_PROJ;
        const float* w1 = cw1 + (size_t)cls * NC1 * D_PROJ;
        #pragma unroll 4
        for (int j = 0; j < 24; j++) {
            const int pr = tid + j * 128;               // 0..3071
            const int lf = chunk * 6144 + pr * 2;       // f4 index in slab (even)
            const int o  = lf >> 8;                      // 0..95
            const int k  = (lf & 255) * 4;               // float offset in row
            const float* src = (o < NC0) ? (w0 + (size_t)o * D_PROJ + k)
                                         : (w1 + (size_t)(o - NC0) * D_PROJ + k);
            float4 v0 = *reinterpret_cast<const float4*>(src);
            float4 v1 = *reinterpret_cast<const float4*>(src + 4);
            uint4 h = { f2h2(v0.y * WSCALE, v0.x * WSCALE), f2h2(v0.w * WSCALE, v0.z * WSCALE),
                        f2h2(v1.y * WSCALE, v1.x * WSCALE), f2h2(v1.w * WSCALE, v1.z * WSCALE) };
            *reinterpret_cast<uint4*>(&g_cwh[(size_t)cls * 96 * D_PROJ + (size_t)lf * 4]) = h;
        }
    }
    signal_done(&g_cwdone[cls]);

    spin_until(&g_bdone, 32);
    const int cnt  = __ldcg(&g_cnt[cls]);
    const int base = chunk * 128;
    if (base >= cnt) return;
    const int ns = min(128, cnt - base);

    spin_until(&g_cwdone[cls], 4);
    spin_until(&g_sdone, 256);

    __shared__ int sidx[128];
    sidx[tid] = __ldcg(&g_idx[cls][base + min(tid, ns - 1)]);
    __syncthreads();

    float acc[2][12][4];
    #pragma unroll
    for (int mt = 0; mt < 2; mt++)
        #pragma unroll
        for (int nt = 0; nt < 12; nt++)
            #pragma unroll
            for (int i = 0; i < 4; i++) acc[mt][nt][i] = 0.f;

    const __half* Bsrc = g_cwh + (size_t)cls * 96 * D_PROJ;

    auto issue = [&](int slot, int t) {
        const uint32_t abase = sb + slot * STC;
        const uint32_t bbase = abase + 16384;
        #pragma unroll
        for (int j = 0; j < 8; j++) {
            const int id = tid + 128 * j;
            const int row = id >> 3, c = id & 7;
            const __half* g = g_sh + (size_t)sidx[row] * D_PROJ + t * 64 + c * 8;
            CP_ASYNC16(abase + row * 128 + ((c ^ (row & 7)) << 4), g);
        }
        #pragma unroll
        for (int j = 0; j < 6; j++) {
            const int id = tid + 128 * j;
            const int row = id >> 3, c = id & 7;
            const __half* g = Bsrc + (size_t)row * D_PROJ + t * 64 + c * 8;
            CP_ASYNC16(bbase + row * 128 + ((c ^ (row & 7)) << 4), g);
        }
    };

    issue(0, 0); CP_COMMIT();
    issue(1, 1); CP_COMMIT();
    int cs = 0, ns_slot = 2;

    for (int t = 0; t < 16; t++) {
        CP_WAIT1();
        __syncthreads();
        const uint32_t abase = sb + cs * STC;
        const uint32_t bbase = abase + 16384;
        if (t + 2 < 16) issue(ns_slot, t + 2);
        CP_COMMIT();

        #pragma unroll
        for (int s = 0; s < 4; s++) {
            uint32_t afr[2][4], bfr[12][2];
            #pragma unroll
            for (int mt = 0; mt < 2; mt++) {
                const int row0 = warp * 32 + mt * 16 + lm_row;
                ldsm_x4(afr[mt], abase + (uint32_t)(row0 * 128)
                                       + ((uint32_t)((2 * s + hi) ^ rm) << 4));
            }
            #pragma unroll
            for (int nb = 0; nb < 6; nb++) {
                uint32_t r[4];
                const int row0 = nb * 16 + lm_row;
                ldsm_x4(r, bbase + (uint32_t)(row0 * 128)
                                 + ((uint32_t)((2 * s + hi) ^ rm) << 4));
                bfr[2 * nb][0] = r[0]; bfr[2 * nb][1] = r[2];
                bfr[2 * nb + 1][0] = r[1]; bfr[2 * nb + 1][1] = r[3];
            }
            #pragma unroll
            for (int mt = 0; mt < 2; mt++)
                #pragma unroll
                for (int nt = 0; nt < 12; nt++)
                    mma_f16(acc[mt][nt], afr[mt], bfr[nt]);
        }
        cs      = (cs == 2) ? 0 : cs + 1;
        ns_slot = (ns_slot == 2) ? 0 : ns_slot + 1;
    }

    #pragma unroll
    for (int mt = 0; mt < 2; mt++) {
        const int s0 = warp * 32 + mt * 16 + gid;
        #pragma unroll
        for (int half = 0; half < 2; half++) {
            const int s = s0 + half * 8;
            if (s < ns) {
                const int g = sidx[s];
                #pragma unroll
                for (int nt = 0; nt < 12; nt++) {
                    const int o = nt * 8 + 2 * tig;
                    const float a0 = acc[mt][nt][2 * half + 0] * OSCALE;
                    const float a1 = acc[mt][nt][2 * half + 1] * OSCALE;
                    if (o < NC0) {
                        float2 v = { a0 + cb0[cls * NC0 + o], a1 + cb0[cls * NC0 + o + 1] };
                        *reinterpret_cast<float2*>(&out[OFF_C0 + g * NC0 + o]) = v;
                    } else {
                        const int o1 = o - NC0;
                        float2 v = { a0 + cb1[cls * NC1 + o1], a1 + cb1[cls * NC1 + o1 + 1] };
                        *reinterpret_cast<float2*>(&out[OFF_C1 + g * NC1 + o1]) = v;
                    }
                }
            }
        }
    }
}

// ===========================================================================
// Launch: 2 kernels total (tiny zero + mega)
// ===========================================================================
extern "C" void kernel_launch(void* const* d_in, const int* in_sizes, int n_in,
                              void* d_out, int out_size)
{
    const float* x   = (const float*)d_in[0];
    const int*   y   = (const int*)  d_in[1];
    const float* Wp  = (const float*)d_in[2];
    const float* bp  = (const float*)d_in[3];
    const float* Ws  = (const float*)d_in[4];
    const float* bs  = (const float*)d_in[5];
    const float* Wc  = (const float*)d_in[6];
    const float* bc  = (const float*)d_in[7];
    const float* cw0 = (const float*)d_in[8];
    const float* cb0 = (const float*)d_in[9];
    const float* cw1 = (const float*)d_in[10];
    const float* cb1 = (const float*)d_in[11];
    float* out = (float*)d_out;

    static bool attr_set = false;
    if (!attr_set) {
        cudaFuncSetAttribute(mega_kernel, cudaFuncAttributeMaxDynamicSharedMemorySize, SMEM_MEGA);
        attr_set = true;
    }

    // 1) zero dependency counters / flags
    zero_kernel<<<1, 256>>>();

    // 2) mega kernel: S-GEMM+convert (z=0), P-GEMM (z=1), tail (z=2)
    dim3 grid(D_PROJ / 128, B_ / 128, 3);   // (8, 32, 3)
    mega_kernel<<<grid, 128, SMEM_MEGA>>>(x, y, Wp, bp, Ws, bs, Wc, bc,
                                          cw0, cb0, cw1, cb1, out);
}

// round 16
// speedup vs baseline: 1.2027x; 1.2027x over previous
#include <cuda_runtime.h>
#include <cuda_fp16.h>
#include <cstdint>

// Problem constants
#define B_     4096
#define D_INN  4096
#define D_PROJ 1024
#define N_CLS  32
#define NC0    32
#define NC1    64

// Output layout: (parent_logits, child0, child1, parent_proj, child_proj) flattened fp32
#define OFF_PLOG 0
#define OFF_C0   (B_ * N_CLS)                 // 131072
#define OFF_C1   (OFF_C0 + B_ * NC0)          // 262144
#define OFF_P    (OFF_C1 + B_ * NC1)          // 524288
#define OFF_S    (OFF_P + B_ * D_PROJ)        // 4718592

#define WSCALE 4096.0f
#define OSCALE (1.0f / 4096.0f)

// fp16 scratch + bucket/dependency state (static device globals)
__device__ __align__(16) __half g_xh[B_ * D_INN];            // 32 MB
__device__ __align__(16) __half g_wph[D_INN * D_PROJ];       // 8 MB (x WSCALE)
__device__ __align__(16) __half g_wsh[D_INN * D_PROJ];       // 8 MB (x WSCALE)
__device__ __align__(16) __half g_ph[B_ * D_PROJ];           // 8 MB, P fp16
__device__ __align__(16) __half g_sh[B_ * D_PROJ];           // 8 MB, S fp16
__device__ __align__(16) __half g_cwh[N_CLS * 96 * D_PROJ];  // 6 MB, merged cw (x WSCALE)
__device__ __align__(16) __half g_wch[D_PROJ * N_CLS];       // 64 KB, Wc (x WSCALE)
__device__ int g_cnt[N_CLS];
__device__ int g_idx[N_CLS][B_];
// dependency counters (zeroed each call by convert_kernel block 0)
__device__ int g_pdone[32];      // per m-row-block of P (target 8)
__device__ int g_sdone;          // S CTAs finished (target 256)
__device__ int g_bdone;          // bucket blocks finished (target 32)
__device__ int g_wcdone;         // Wc-convert blocks finished (target 32)
__device__ int g_cwdone[N_CLS];  // per-class cw-convert quarters (target 4)

// ===========================================================================
// helpers
// ===========================================================================
__device__ __forceinline__ uint32_t smem_u32(const void* p) {
    uint32_t a;
    asm("{ .reg .u64 t; cvta.to.shared.u64 t, %1; cvt.u32.u64 %0, t; }" : "=r"(a) : "l"(p));
    return a;
}

__device__ __forceinline__ uint32_t f2h2(float hi, float lo) {
    uint32_t r;
    asm("cvt.rn.f16x2.f32 %0, %1, %2;" : "=r"(r) : "f"(hi), "f"(lo));
    return r;
}

__device__ __forceinline__ void ldsm_x4(uint32_t* r, uint32_t addr) {
    asm volatile("ldmatrix.sync.aligned.m8n8.x4.shared.b16 {%0,%1,%2,%3}, [%4];"
                 : "=r"(r[0]), "=r"(r[1]), "=r"(r[2]), "=r"(r[3]) : "r"(addr));
}
__device__ __forceinline__ void ldsm_x4_t(uint32_t* r, uint32_t addr) {
    asm volatile("ldmatrix.sync.aligned.m8n8.x4.trans.shared.b16 {%0,%1,%2,%3}, [%4];"
                 : "=r"(r[0]), "=r"(r[1]), "=r"(r[2]), "=r"(r[3]) : "r"(addr));
}

__device__ __forceinline__ void mma_f16(float* d, const uint32_t* a, const uint32_t* b) {
    asm volatile(
        "mma.sync.aligned.m16n8k16.row.col.f32.f16.f16.f32 "
        "{%0,%1,%2,%3}, {%4,%5,%6,%7}, {%8,%9}, {%0,%1,%2,%3};"
        : "+f"(d[0]), "+f"(d[1]), "+f"(d[2]), "+f"(d[3])
        : "r"(a[0]), "r"(a[1]), "r"(a[2]), "r"(a[3]), "r"(b[0]), "r"(b[1]));
}

#define CP_ASYNC16(saddr, gaddr) \
    asm volatile("cp.async.cg.shared.global [%0], [%1], 16;" :: "r"(saddr), "l"(gaddr))
#define CP_COMMIT() asm volatile("cp.async.commit_group;" ::: "memory")
#define CP_WAIT1()  asm volatile("cp.async.wait_group 1;"  ::: "memory")

// Completion signal: all threads' stores -> fence -> sync -> one atomic.
__device__ __forceinline__ void signal_done(int* ctr) {
    __threadfence();
    __syncthreads();
    if (threadIdx.x == 0) atomicAdd(ctr, 1);
}
// Spin until *ctr >= target (device-scope atomic read), then fence.
__device__ __forceinline__ void spin_until(int* ctr, int target) {
    if (threadIdx.x == 0)
        while (atomicAdd(ctr, 0) < target) __nanosleep(128);
    __syncthreads();
    __threadfence();
}

// ===========================================================================
// K0: fp32 -> fp16 pre-conversion of x, Wp*WS, Ws*WS + counter zeroing.
// 16 floats per thread (4 consecutive float4 -> 2 uint4 stores).
// All region sizes are divisible by 4 float4-units: no boundary straddles.
// ===========================================================================
#define NXF4  (B_ * D_INN / 4)           // 4194304
#define NWF4  (D_INN * D_PROJ / 4)       // 1048576
#define NCONVA (NXF4 + 2 * NWF4)         // 6291456
#define NCONVA4 (NCONVA / 4)             // 1572864 threads

__global__ __launch_bounds__(256)
void convert_kernel(const float* __restrict__ x,
                    const float* __restrict__ Wp, const float* __restrict__ Ws)
{
    if (blockIdx.x == 0) {
        const int t = threadIdx.x;
        if (t < N_CLS) { g_cnt[t] = 0; g_pdone[t] = 0; g_cwdone[t] = 0; }
        else if (t == 32) g_sdone = 0;
        else if (t == 33) g_bdone = 0;
        else if (t == 34) g_wcdone = 0;
    }

    const int p = blockIdx.x * blockDim.x + threadIdx.x;   // quad index
    if (p >= NCONVA4) return;
    const int i = p * 4;                                   // first float4 index

    const float* src;
    __half* dst;
    float sc;
    int j;
    if (i < NXF4)                  { src = x;  dst = g_xh;  sc = 1.0f;   j = i; }
    else if (i < NXF4 + NWF4)      { src = Wp; dst = g_wph; sc = WSCALE; j = i - NXF4; }
    else                           { src = Ws; dst = g_wsh; sc = WSCALE; j = i - NXF4 - NWF4; }

    const size_t f = (size_t)j * 4;
    float4 v0 = *reinterpret_cast<const float4*>(src + f);
    float4 v1 = *reinterpret_cast<const float4*>(src + f + 4);
    float4 v2 = *reinterpret_cast<const float4*>(src + f + 8);
    float4 v3 = *reinterpret_cast<const float4*>(src + f + 12);
    uint4 h0 = { f2h2(v0.y * sc, v0.x * sc), f2h2(v0.w * sc, v0.z * sc),
                 f2h2(v1.y * sc, v1.x * sc), f2h2(v1.w * sc, v1.z * sc) };
    uint4 h1 = { f2h2(v2.y * sc, v2.x * sc), f2h2(v2.w * sc, v2.z * sc),
                 f2h2(v3.y * sc, v3.x * sc), f2h2(v3.w * sc, v3.z * sc) };
    *reinterpret_cast<uint4*>(&dst[f])     = h0;
    *reinterpret_cast<uint4*>(&dst[f + 8]) = h1;
}

// ===========================================================================
// Mega kernel (R12 core, proven at 193 us), grid (8, 32, 3), 128 threads:
// z=0: S = x@Ws GEMM -> g_sdone
// z=1: P = x@Wp GEMM -> g_pdone[by]
// z=2: flat<32 bucket; 32..63 plog (convert Wc, wait, TC plog);
//      64..191 child (convert cw quarter, wait, TC child); rest exit.
// ===========================================================================
#define STAGES 3
#define BKH    64
#define A_ST_BYTES (128 * 128)               // 16384
#define B_ST_BYTES (64 * 256)                // 16384
#define ST_BYTES   (A_ST_BYTES + B_ST_BYTES) // 32768
#define SMEM_MEGA  (STAGES * ST_BYTES)       // 98304

#define STP (16384 + 64 * 80)    // 21504  (plog stage)
#define STC (16384 + 96 * 128)   // 28672  (child stage)

__global__ __launch_bounds__(128, 2)
void mega_kernel(const int* __restrict__ y,
                 const float* __restrict__ bp, const float* __restrict__ bs,
                 const float* __restrict__ Wc, const float* __restrict__ bc,
                 const float* __restrict__ cw0, const float* __restrict__ cb0,
                 const float* __restrict__ cw1, const float* __restrict__ cb1,
                 float* __restrict__ out)
{
    extern __shared__ char sm[];
    const uint32_t sb = smem_u32(sm);

    const int tid  = threadIdx.x;
    const int warp = tid >> 5;
    const int lane = tid & 31;
    const int lm_row = (lane & 7) + ((lane >> 3) & 1) * 8;  // 0..15
    const int hi     = lane >> 4;                           // 0..1
    const int rm     = lm_row & 7;
    const int gid    = lane >> 2;
    const int tig    = lane & 3;

    const int z = blockIdx.z;

    if (z < 2) {
        // =================== GEMM planes (R10 core) ===================
        const __half* __restrict__ Wh  = (z == 0) ? g_wsh : g_wph;
        const float*  __restrict__ bias = (z == 0) ? bs : bp;
        float* __restrict__ C  = out + ((z == 0) ? OFF_S : OFF_P);
        __half* __restrict__ Ch = (z == 0) ? g_sh : g_ph;

        const int wm   = warp >> 1;   // 0..1
        const int wn   = warp & 1;    // 0..1
        const int mblk = blockIdx.y * 128;
        const int nblk = blockIdx.x * 128;

        float acc[4][8][4];
        #pragma unroll
        for (int mt = 0; mt < 4; mt++)
            #pragma unroll
            for (int nt = 0; nt < 8; nt++)
                #pragma unroll
                for (int i = 0; i < 4; i++) acc[mt][nt][i] = 0.f;

        auto issue = [&](uint32_t abase, int t) {
            const uint32_t bbase = abase + A_ST_BYTES;
            #pragma unroll
            for (int j = 0; j < 8; j++) {
                const int id  = tid + 128 * j;
                const int row = id >> 3, c = id & 7;
                const __half* g = g_xh + (size_t)(mblk + row) * D_INN + t * BKH + c * 8;
                CP_ASYNC16(abase + row * 128 + ((c ^ (row & 7)) << 4), g);
            }
            #pragma unroll
            for (int j = 0; j < 8; j++) {
                const int id = tid + 128 * j;
                const int k  = id >> 4, c = id & 15;
                const __half* g = Wh + (size_t)(t * BKH + k) * D_PROJ + nblk + c * 8;
                CP_ASYNC16(bbase + k * 256 + ((c ^ (k & 7)) << 4), g);
            }
        };

        auto load_frags = [&](uint32_t abase, int s, uint32_t (&af)[4][4], uint32_t (&bf)[8][2]) {
            const uint32_t bbase = abase + A_ST_BYTES;
            #pragma unroll
            for (int mt = 0; mt < 4; mt++) {
                const int row0 = wm * 64 + mt * 16 + lm_row;
                ldsm_x4(af[mt], abase + (uint32_t)(row0 * 128)
                                      + ((uint32_t)((2 * s + hi) ^ rm) << 4));
            }
            #pragma unroll
            for (int nb = 0; nb < 4; nb++) {
                uint32_t r[4];
                const int krow = 16 * s + lm_row;
                ldsm_x4_t(r, bbase + (uint32_t)(krow * 256)
                                   + ((uint32_t)((wn * 8 + nb * 2 + hi) ^ rm) << 4));
                bf[2 * nb][0] = r[0]; bf[2 * nb][1] = r[1];
                bf[2 * nb + 1][0] = r[2]; bf[2 * nb + 1][1] = r[3];
            }
        };

        uint32_t afr[2][4][4], bfr[2][8][2];

        auto body = [&](int t, uint32_t cbase, uint32_t pbase) {
            CP_WAIT1();
            __syncthreads();

            load_frags(cbase, 0, afr[0], bfr[0]);

            if (t + 2 < 64)
                issue(pbase, t + 2);
            CP_COMMIT();

            #pragma unroll
            for (int s = 0; s < 4; s++) {
                if (s < 3)
                    load_frags(cbase, s + 1, afr[(s + 1) & 1], bfr[(s + 1) & 1]);
                const int cur = s & 1;
                #pragma unroll
                for (int mt = 0; mt < 4; mt++)
                    #pragma unroll
                    for (int nt = 0; nt < 8; nt++)
                        mma_f16(acc[mt][nt], afr[cur][mt], bfr[cur][nt]);
            }
        };

        const uint32_t s0 = sb, s1 = sb + ST_BYTES, s2 = sb + 2 * ST_BYTES;

        issue(s0, 0); CP_COMMIT();
        issue(s1, 1); CP_COMMIT();

        for (int t = 0; t < 63; t += 3) {
            body(t,     s0, s2);
            body(t + 1, s1, s0);
            body(t + 2, s2, s1);
        }
        body(63, s0, s2);

        #pragma unroll
        for (int mt = 0; mt < 4; mt++) {
            const int row = mblk + wm * 64 + mt * 16 + gid;
            #pragma unroll
            for (int nt = 0; nt < 8; nt++) {
                const int col = nblk + wn * 64 + nt * 8 + 2 * tig;
                const float b0 = bias[col], b1 = bias[col + 1];
                float2 v0 = { acc[mt][nt][0] * OSCALE + b0, acc[mt][nt][1] * OSCALE + b1 };
                float2 v1 = { acc[mt][nt][2] * OSCALE + b0, acc[mt][nt][3] * OSCALE + b1 };
                *reinterpret_cast<float2*>(&C[(size_t)row * D_PROJ + col])       = v0;
                *reinterpret_cast<float2*>(&C[(size_t)(row + 8) * D_PROJ + col]) = v1;
                *reinterpret_cast<uint32_t*>(&Ch[(size_t)row * D_PROJ + col])       = f2h2(v0.y, v0.x);
                *reinterpret_cast<uint32_t*>(&Ch[(size_t)(row + 8) * D_PROJ + col]) = f2h2(v1.y, v1.x);
            }
        }

        signal_done((z == 0) ? &g_sdone : &g_pdone[blockIdx.y]);
        return;
    }

    // ======================= z == 2 : tail plane =======================
    const int flat = blockIdx.x + 8 * blockIdx.y;   // 0..255

    if (flat < 32) {
        // ---- bucket: 32 blocks x 128 threads = 4096 samples ----
        const int b = flat * 128 + tid;
        const int c = y[b];
        const int p = atomicAdd(&g_cnt[c], 1);
        g_idx[c][p] = b;
        signal_done(&g_bdone);
        return;
    }

    if (flat < 64) {
        // ---- parent logits block ----
        const int by   = flat - 32;
        const int mblk = by * 128;

        // convert this block's Wc slice (128 pairs of float4)
        {
            const int q = by * 128 + tid;          // 0..4095
            const size_t f4 = (size_t)q * 2;
            float4 v0 = *reinterpret_cast<const float4*>(Wc + f4 * 4);
            float4 v1 = *reinterpret_cast<const float4*>(Wc + f4 * 4 + 4);
            uint4 h = { f2h2(v0.y * WSCALE, v0.x * WSCALE), f2h2(v0.w * WSCALE, v0.z * WSCALE),
                        f2h2(v1.y * WSCALE, v1.x * WSCALE), f2h2(v1.w * WSCALE, v1.z * WSCALE) };
            *reinterpret_cast<uint4*>(&g_wch[f4 * 4]) = h;
        }
        signal_done(&g_wcdone);
        spin_until(&g_wcdone, 32);
        spin_until(&g_pdone[by], 8);

        float acc[2][4][4];
        #pragma unroll
        for (int mt = 0; mt < 2; mt++)
            #pragma unroll
            for (int nt = 0; nt < 4; nt++)
                #pragma unroll
                for (int i = 0; i < 4; i++) acc[mt][nt][i] = 0.f;

        auto issue = [&](int slot, int t) {
            const uint32_t abase = sb + slot * STP;
            const uint32_t bbase = abase + 16384;
            #pragma unroll
            for (int j = 0; j < 8; j++) {
                const int id = tid + 128 * j;
                const int row = id >> 3, c = id & 7;
                const __half* g = g_ph + (size_t)(mblk + row) * D_PROJ + t * 64 + c * 8;
                CP_ASYNC16(abase + row * 128 + ((c ^ (row & 7)) << 4), g);
            }
            #pragma unroll
            for (int j = 0; j < 2; j++) {
                const int id = tid + 128 * j;
                const int row = id >> 2, c = id & 3;
                const __half* g = g_wch + (size_t)(t * 64 + row) * N_CLS + c * 8;
                CP_ASYNC16(bbase + row * 80 + c * 16, g);
            }
        };

        issue(0, 0); CP_COMMIT();
        issue(1, 1); CP_COMMIT();
        int cs = 0, ns_slot = 2;

        for (int t = 0; t < 16; t++) {
            CP_WAIT1();
            __syncthreads();
            const uint32_t abase = sb + cs * STP;
            const uint32_t bbase = abase + 16384;
            if (t + 2 < 16) issue(ns_slot, t + 2);
            CP_COMMIT();

            #pragma unroll
            for (int s = 0; s < 4; s++) {
                uint32_t afr[2][4], bfr[4][2];
                #pragma unroll
                for (int mt = 0; mt < 2; mt++) {
                    const int row0 = warp * 32 + mt * 16 + lm_row;
                    ldsm_x4(afr[mt], abase + (uint32_t)(row0 * 128)
                                           + ((uint32_t)((2 * s + hi) ^ rm) << 4));
                }
                #pragma unroll
                for (int nb = 0; nb < 2; nb++) {
                    uint32_t r[4];
                    const int krow = 16 * s + lm_row;
                    ldsm_x4_t(r, bbase + (uint32_t)(krow * 80)
                                       + (uint32_t)((nb * 2 + hi) * 16));
                    bfr[2 * nb][0] = r[0]; bfr[2 * nb][1] = r[1];
                    bfr[2 * nb + 1][0] = r[2]; bfr[2 * nb + 1][1] = r[3];
                }
                #pragma unroll
                for (int mt = 0; mt < 2; mt++)
                    #pragma unroll
                    for (int nt = 0; nt < 4; nt++)
                        mma_f16(acc[mt][nt], afr[mt], bfr[nt]);
            }
            cs      = (cs == 2) ? 0 : cs + 1;
            ns_slot = (ns_slot == 2) ? 0 : ns_slot + 1;
        }

        #pragma unroll
        for (int mt = 0; mt < 2; mt++) {
            const int row = mblk + warp * 32 + mt * 16 + gid;
            #pragma unroll
            for (int nt = 0; nt < 4; nt++) {
                const int col = nt * 8 + 2 * tig;
                const float b0 = bc[col], b1 = bc[col + 1];
                float2 v0 = { acc[mt][nt][0] * OSCALE + b0, acc[mt][nt][1] * OSCALE + b1 };
                float2 v1 = { acc[mt][nt][2] * OSCALE + b0, acc[mt][nt][3] * OSCALE + b1 };
                *reinterpret_cast<float2*>(&out[OFF_PLOG + row * N_CLS + col])       = v0;
                *reinterpret_cast<float2*>(&out[OFF_PLOG + (row + 8) * N_CLS + col]) = v1;
            }
        }
        return;
    }

    if (flat >= 192) return;

    // ---- child expert block ----
    const int cbk   = flat - 64;
    const int cls   = cbk >> 2;
    const int chunk = cbk & 3;

    // convert this block's quarter of the class cw slab
    {
        const float* w0 = cw0 + (size_t)cls * NC0 * D_PROJ;
        const float* w1 = cw1 + (size_t)cls * NC1 * D_PROJ;
        #pragma unroll 4
        for (int j = 0; j < 24; j++) {
            const int pr = tid + j * 128;               // 0..3071
            const int lf = chunk * 6144 + pr * 2;       // f4 index in slab (even)
            const int o  = lf >> 8;                      // 0..95
            const int k  = (lf & 255) * 4;               // float offset in row
            const float* src = (o < NC0) ? (w0 + (size_t)o * D_PROJ + k)
                                         : (w1 + (size_t)(o - NC0) * D_PROJ + k);
            float4 v0 = *reinterpret_cast<const float4*>(src);
            float4 v1 = *reinterpret_cast<const float4*>(src + 4);
            uint4 h = { f2h2(v0.y * WSCALE, v0.x * WSCALE), f2h2(v0.w * WSCALE, v0.z * WSCALE),
                        f2h2(v1.y * WSCALE, v1.x * WSCALE), f2h2(v1.w * WSCALE, v1.z * WSCALE) };
            *reinterpret_cast<uint4*>(&g_cwh[(size_t)cls * 96 * D_PROJ + (size_t)lf * 4]) = h;
        }
    }
    signal_done(&g_cwdone[cls]);

    spin_until(&g_bdone, 32);
    const int cnt  = __ldcg(&g_cnt[cls]);
    const int base = chunk * 128;
    if (base >= cnt) return;
    const int ns = min(128, cnt - base);

    spin_until(&g_cwdone[cls], 4);
    spin_until(&g_sdone, 256);

    __shared__ int sidx[128];
    sidx[tid] = __ldcg(&g_idx[cls][base + min(tid, ns - 1)]);
    __syncthreads();

    float acc[2][12][4];
    #pragma unroll
    for (int mt = 0; mt < 2; mt++)
        #pragma unroll
        for (int nt = 0; nt < 12; nt++)
            #pragma unroll
            for (int i = 0; i < 4; i++) acc[mt][nt][i] = 0.f;

    const __half* Bsrc = g_cwh + (size_t)cls * 96 * D_PROJ;

    auto issue = [&](int slot, int t) {
        const uint32_t abase = sb + slot * STC;
        const uint32_t bbase = abase + 16384;
        #pragma unroll
        for (int j = 0; j < 8; j++) {
            const int id = tid + 128 * j;
            const int row = id >> 3, c = id & 7;
            const __half* g = g_sh + (size_t)sidx[row] * D_PROJ + t * 64 + c * 8;
            CP_ASYNC16(abase + row * 128 + ((c ^ (row & 7)) << 4), g);
        }
        #pragma unroll
        for (int j = 0; j < 6; j++) {
            const int id = tid + 128 * j;
            const int row = id >> 3, c = id & 7;
            const __half* g = Bsrc + (size_t)row * D_PROJ + t * 64 + c * 8;
            CP_ASYNC16(bbase + row * 128 + ((c ^ (row & 7)) << 4), g);
        }
    };

    issue(0, 0); CP_COMMIT();
    issue(1, 1); CP_COMMIT();
    int cs = 0, ns_slot = 2;

    for (int t = 0; t < 16; t++) {
        CP_WAIT1();
        __syncthreads();
        const uint32_t abase = sb + cs * STC;
        const uint32_t bbase = abase + 16384;
        if (t + 2 < 16) issue(ns_slot, t + 2);
        CP_COMMIT();

        #pragma unroll
        for (int s = 0; s < 4; s++) {
            uint32_t afr[2][4], bfr[12][2];
            #pragma unroll
            for (int mt = 0; mt < 2; mt++) {
                const int row0 = warp * 32 + mt * 16 + lm_row;
                ldsm_x4(afr[mt], abase + (uint32_t)(row0 * 128)
                                       + ((uint32_t)((2 * s + hi) ^ rm) << 4));
            }
            #pragma unroll
            for (int nb = 0; nb < 6; nb++) {
                uint32_t r[4];
                const int row0 = nb * 16 + lm_row;
                ldsm_x4(r, bbase + (uint32_t)(row0 * 128)
                                 + ((uint32_t)((2 * s + hi) ^ rm) << 4));
                bfr[2 * nb][0] = r[0]; bfr[2 * nb][1] = r[2];
                bfr[2 * nb + 1][0] = r[1]; bfr[2 * nb + 1][1] = r[3];
            }
            #pragma unroll
            for (int mt = 0; mt < 2; mt++)
                #pragma unroll
                for (int nt = 0; nt < 12; nt++)
                    mma_f16(acc[mt][nt], afr[mt], bfr[nt]);
        }
        cs      = (cs == 2) ? 0 : cs + 1;
        ns_slot = (ns_slot == 2) ? 0 : ns_slot + 1;
    }

    #pragma unroll
    for (int mt = 0; mt < 2; mt++) {
        const int s0 = warp * 32 + mt * 16 + gid;
        #pragma unroll
        for (int half = 0; half < 2; half++) {
            const int s = s0 + half * 8;
            if (s < ns) {
                const int g = sidx[s];
                #pragma unroll
                for (int nt = 0; nt < 12; nt++) {
                    const int o = nt * 8 + 2 * tig;
                    const float a0 = acc[mt][nt][2 * half + 0] * OSCALE;
                    const float a1 = acc[mt][nt][2 * half + 1] * OSCALE;
                    if (o < NC0) {
                        float2 v = { a0 + cb0[cls * NC0 + o], a1 + cb0[cls * NC0 + o + 1] };
                        *reinterpret_cast<float2*>(&out[OFF_C0 + g * NC0 + o]) = v;
                    } else {
                        const int o1 = o - NC0;
                        float2 v = { a0 + cb1[cls * NC1 + o1], a1 + cb1[cls * NC1 + o1 + 1] };
                        *reinterpret_cast<float2*>(&out[OFF_C1 + g * NC1 + o1]) = v;
                    }
                }
            }
        }
    }
}

// ===========================================================================
// Launch: 2 kernels total
// ===========================================================================
extern "C" void kernel_launch(void* const* d_in, const int* in_sizes, int n_in,
                              void* d_out, int out_size)
{
    const float* x   = (const float*)d_in[0];
    const int*   y   = (const int*)  d_in[1];
    const float* Wp  = (const float*)d_in[2];
    const float* bp  = (const float*)d_in[3];
    const float* Ws  = (const float*)d_in[4];
    const float* bs  = (const float*)d_in[5];
    const float* Wc  = (const float*)d_in[6];
    const float* bc  = (const float*)d_in[7];
    const float* cw0 = (const float*)d_in[8];
    const float* cb0 = (const float*)d_in[9];
    const float* cw1 = (const float*)d_in[10];
    const float* cb1 = (const float*)d_in[11];
    float* out = (float*)d_out;

    static bool attr_set = false;
    if (!attr_set) {
        cudaFuncSetAttribute(mega_kernel, cudaFuncAttributeMaxDynamicSharedMemorySize, SMEM_MEGA);
        attr_set = true;
    }

    // 1) fp16 pre-conversion of x/Wp/Ws (16 floats/thread) + counter zeroing
    convert_kernel<<<(NCONVA4 + 255) / 256, 256>>>(x, Wp, Ws);

    // 2) mega kernel: S-GEMM (z=0), P-GEMM (z=1), tail (z=2)
    dim3 grid(D_PROJ / 128, B_ / 128, 3);   // (8, 32, 3)
    mega_kernel<<<grid, 128, SMEM_MEGA>>>(y, bp, bs, Wc, bc, cw0, cb0, cw1, cb1, out);
}